// round 1
// baseline (speedup 1.0000x reference)
#include <cuda_runtime.h>

#define BATCH 4
#define SEQLEN 4096
#define DMODEL 1024
#define DSTATE 16
#define NROWS (BATCH*SEQLEN)

// Scratch (device globals: allocation-free per harness rules)
__device__ float g_bx[NROWS*DSTATE];
__device__ float g_decay[NROWS*DSTATE];
__device__ float g_hs[NROWS*DSTATE];

// ---------------------------------------------------------------------------
// Kernel 1: Bx = x @ B_in ; decay = exp(softplus(Bx) * (-exp(A)))
// One warp handles 4 rows. Lane l covers elements e = k*128 + 4l (k=0..7).
// ---------------------------------------------------------------------------
__global__ __launch_bounds__(256) void bx_kernel(const float* __restrict__ x,
                                                 const float* __restrict__ A,
                                                 const float* __restrict__ B_in) {
    const int warp = threadIdx.x >> 5;
    const int lane = threadIdx.x & 31;
    const int r0 = (blockIdx.x * 8 + warp) * 4;

    float acc[4][16];
#pragma unroll
    for (int r = 0; r < 4; r++)
#pragma unroll
        for (int s = 0; s < 16; s++) acc[r][s] = 0.f;

#pragma unroll
    for (int k = 0; k < 8; k++) {
        const int ebase = k * 128 + lane * 4;
        float4 xv[4];
#pragma unroll
        for (int r = 0; r < 4; r++)
            xv[r] = *(const float4*)(x + (size_t)(r0 + r) * DMODEL + ebase);
#pragma unroll
        for (int j = 0; j < 4; j++) {
            const float4* bp = (const float4*)(B_in + (size_t)(ebase + j) * DSTATE);
            float brow[16];
            *(float4*)&brow[0]  = bp[0];
            *(float4*)&brow[4]  = bp[1];
            *(float4*)&brow[8]  = bp[2];
            *(float4*)&brow[12] = bp[3];
#pragma unroll
            for (int r = 0; r < 4; r++) {
                const float xj = ((const float*)&xv[r])[j];
#pragma unroll
                for (int s = 0; s < 16; s++)
                    acc[r][s] = fmaf(xj, brow[s], acc[r][s]);
            }
        }
    }

    // Butterfly reduce each of the 64 partials across the warp
#pragma unroll
    for (int r = 0; r < 4; r++)
#pragma unroll
        for (int s = 0; s < 16; s++) {
#pragma unroll
            for (int off = 16; off; off >>= 1)
                acc[r][s] += __shfl_xor_sync(0xffffffffu, acc[r][s], off);
        }

    if (lane < 16) {
        const int s = lane;
        const float an = -expf(A[s]);   // A_neg
#pragma unroll
        for (int r = 0; r < 4; r++) {
            const float bx = acc[r][s];
            const float sp = (bx > 20.f) ? bx : log1pf(expf(bx));
            const float dec = expf(sp * an);
            const size_t idx = (size_t)(r0 + r) * DSTATE + s;
            g_bx[idx] = bx;
            g_decay[idx] = dec;
        }
    }
}

// ---------------------------------------------------------------------------
// Kernel 2: chunked affine scan. One block per (b, s) sequence (64 blocks).
// 256 threads x 16 steps; Hillis-Steele scan over chunk summaries (a, h):
// composing E=(pa,ph) then local (a,h): A = a*pa, H = a*ph + h.
// ---------------------------------------------------------------------------
__global__ __launch_bounds__(256) void scan_kernel() {
    const int b = blockIdx.x >> 4;
    const int s = blockIdx.x & 15;
    const int t = threadIdx.x;
    const int CH = SEQLEN / 256;   // 16

    const size_t base = ((size_t)b * SEQLEN + (size_t)t * CH) * DSTATE + s;
    float d[CH], v[CH];
#pragma unroll
    for (int i = 0; i < CH; i++) {
        d[i] = g_decay[base + (size_t)i * DSTATE];
        v[i] = g_bx[base + (size_t)i * DSTATE];
    }

    float a = 1.f, h = 0.f;
#pragma unroll
    for (int i = 0; i < CH; i++) { h = fmaf(h, d[i], v[i]); a *= d[i]; }

    __shared__ float sA[256], sH[256];
    sA[t] = a; sH[t] = h;
    __syncthreads();
#pragma unroll
    for (int off = 1; off < 256; off <<= 1) {
        float pa = 1.f, ph = 0.f;
        const bool act = (t >= off);
        if (act) { pa = sA[t - off]; ph = sH[t - off]; }
        __syncthreads();
        if (act) {
            h = fmaf(a, ph, h);
            a = a * pa;
            sA[t] = a; sH[t] = h;
        }
        __syncthreads();
    }

    float hp = (t == 0) ? 0.f : sH[t - 1];
#pragma unroll
    for (int i = 0; i < CH; i++) {
        hp = fmaf(hp, d[i], v[i]);
        g_hs[base + (size_t)i * DSTATE] = hp;
    }
}

// ---------------------------------------------------------------------------
// Kernel 3: y = hs @ C + x * D
// One block per 64 rows; thread t owns output columns [4t, 4t+4); C tile for
// those 4 columns kept in 16 float4 registers; hs tile staged in shared.
// ---------------------------------------------------------------------------
__global__ __launch_bounds__(256) void out_kernel(const float* __restrict__ x,
                                                  const float* __restrict__ C,
                                                  const float* __restrict__ D,
                                                  float* __restrict__ y) {
    __shared__ float sh[64 * 16];
    const int t = threadIdx.x;
    const int row0 = blockIdx.x * 64;

#pragma unroll
    for (int i = 0; i < 4; i++)
        sh[t + 256 * i] = g_hs[(size_t)row0 * DSTATE + t + 256 * i];
    __syncthreads();

    float4 c4[16];
#pragma unroll
    for (int s = 0; s < 16; s++)
        c4[s] = *(const float4*)(C + (size_t)s * DMODEL + 4 * t);
    const float4 d4 = *(const float4*)(D + 4 * t);

    for (int r = 0; r < 64; r++) {
        const float* hr = &sh[r * 16];
        const float4 x4 = *(const float4*)(x + (size_t)(row0 + r) * DMODEL + 4 * t);
        float4 acc;
        acc.x = x4.x * d4.x;
        acc.y = x4.y * d4.y;
        acc.z = x4.z * d4.z;
        acc.w = x4.w * d4.w;
#pragma unroll
        for (int s = 0; s < 16; s++) {
            const float f = hr[s];
            acc.x = fmaf(f, c4[s].x, acc.x);
            acc.y = fmaf(f, c4[s].y, acc.y);
            acc.z = fmaf(f, c4[s].z, acc.z);
            acc.w = fmaf(f, c4[s].w, acc.w);
        }
        *(float4*)(y + (size_t)(row0 + r) * DMODEL + 4 * t) = acc;
    }
}

extern "C" void kernel_launch(void* const* d_in, const int* in_sizes, int n_in,
                              void* d_out, int out_size) {
    const float* x    = (const float*)d_in[0];   // [4,4096,1024]
    const float* A    = (const float*)d_in[1];   // [1,16]
    const float* B_in = (const float*)d_in[2];   // [1024,16]
    const float* C    = (const float*)d_in[3];   // [16,1024]
    const float* D    = (const float*)d_in[4];   // [1024]
    float* y = (float*)d_out;                    // [4,4096,1024]

    bx_kernel<<<512, 256>>>(x, A, B_in);
    scan_kernel<<<64, 256>>>();
    out_kernel<<<256, 256>>>(x, C, D, y);
}

// round 2
// speedup vs baseline: 1.2815x; 1.2815x over previous
#include <cuda_runtime.h>

#define BATCH 4
#define SEQLEN 4096
#define DMODEL 1024
#define DSTATE 16
#define NROWS (BATCH*SEQLEN)

// Scratch in [b][s][n] layout (contiguous per scan sequence)
__device__ float g_bx[NROWS*DSTATE];
__device__ float g_decay[NROWS*DSTATE];
__device__ float g_hs[NROWS*DSTATE];

// ---- packed f32x2 helpers (FFMA2 only reachable via PTX) --------------------
__device__ __forceinline__ double pk2(float lo, float hi) {
    double d; asm("mov.b64 %0, {%1, %2};" : "=d"(d) : "f"(lo), "f"(hi)); return d;
}
__device__ __forceinline__ double fma2(double a, double b, double c) {
    double d; asm("fma.rn.f32x2 %0, %1, %2, %3;" : "=d"(d) : "d"(a), "d"(b), "d"(c)); return d;
}
__device__ __forceinline__ double add2(double a, double b) {
    double d; asm("add.rn.f32x2 %0, %1, %2;" : "=d"(d) : "d"(a), "d"(b)); return d;
}
__device__ __forceinline__ float lo2(double d) { return __int_as_float(__double2loint(d)); }
__device__ __forceinline__ float hi2(double d) { return __int_as_float(__double2hiint(d)); }

// ---------------------------------------------------------------------------
// Kernel 1: Bx = x @ B_in ; decay = exp(softplus(Bx) * -exp(A))
// Block: 256 threads, 32 rows (8 threads/row). Thread (rloc, c) covers
// e = c + 8k. x loads are coalesced LDG.32 (4 rows x 32B full sectors/warp).
// B chunk staged in shared, pitch 20 floats -> conflict-free double2 loads.
// Accumulation in 8 packed f32x2 regs; 3-stage shuffle reduce over c.
// Output written transposed to [b][s][n].
// ---------------------------------------------------------------------------
__global__ __launch_bounds__(256) void bx_kernel(const float* __restrict__ x,
                                                 const float* __restrict__ A,
                                                 const float* __restrict__ B_in) {
    __shared__ __align__(16) float sb[256 * 20];   // 20 KB (256-e chunk, pitch 20)
    __shared__ double sdump[32 * 8];               // 2 KB reduce spill

    const int t = threadIdx.x;
    const int c = t & 7;
    const int rloc = t >> 3;
    const int row = blockIdx.x * 32 + rloc;        // global row = b*4096 + n

    double acc[8];
#pragma unroll
    for (int i = 0; i < 8; i++) acc[i] = 0.0;      // bit-zero == (0.f,0.f)

    for (int ch = 0; ch < 4; ch++) {
        __syncthreads();
        // stage B[ch*256 .. +256) -> sb (pitch 20)
#pragma unroll
        for (int i = 0; i < 16; i++) {
            int idx = i * 256 + t;                 // 0..4095
            int e = idx >> 4, s = idx & 15;
            sb[e * 20 + s] = B_in[(size_t)(ch * 256 + e) * DSTATE + s];
        }
        __syncthreads();

        const float* xp = x + (size_t)row * DMODEL + ch * 256 + c;
#pragma unroll
        for (int k = 0; k < 32; k++) {
            const float xv = xp[k * 8];
            const double xx = pk2(xv, xv);
            const double2* bp = (const double2*)(sb + (c + k * 8) * 20);
            const double2 b0 = bp[0], b1 = bp[1], b2 = bp[2], b3 = bp[3];
            acc[0] = fma2(xx, b0.x, acc[0]);
            acc[1] = fma2(xx, b0.y, acc[1]);
            acc[2] = fma2(xx, b1.x, acc[2]);
            acc[3] = fma2(xx, b1.y, acc[3]);
            acc[4] = fma2(xx, b2.x, acc[4]);
            acc[5] = fma2(xx, b2.y, acc[5]);
            acc[6] = fma2(xx, b3.x, acc[6]);
            acc[7] = fma2(xx, b3.y, acc[7]);
        }
    }

    // reduce over the 8 c-lanes (xor within groups of 8)
#pragma unroll
    for (int off = 1; off < 8; off <<= 1) {
#pragma unroll
        for (int i = 0; i < 8; i++) {
            double o = __shfl_xor_sync(0xffffffffu, acc[i], off);
            acc[i] = add2(acc[i], o);
        }
    }

    __syncthreads();
    if (c == 0) {
#pragma unroll
        for (int i = 0; i < 8; i++) sdump[rloc * 8 + i] = acc[i];
    }
    __syncthreads();

    // thread handles s = 2c, 2c+1 for its row
    const double mysum = sdump[rloc * 8 + c];
    const float bx0 = lo2(mysum), bx1 = hi2(mysum);
    const int s0 = 2 * c;
    const float an0 = -expf(A[s0]);
    const float an1 = -expf(A[s0 + 1]);
    const float sp0 = (bx0 > 20.f) ? bx0 : log1pf(expf(bx0));
    const float sp1 = (bx1 > 20.f) ? bx1 : log1pf(expf(bx1));
    const float d0 = expf(sp0 * an0);
    const float d1 = expf(sp1 * an1);

    const int b = row >> 12, n = row & 4095;
    const size_t o0 = ((size_t)(b * DSTATE + s0)) * SEQLEN + n;
    g_bx[o0] = bx0;            g_bx[o0 + SEQLEN] = bx1;
    g_decay[o0] = d0;          g_decay[o0 + SEQLEN] = d1;
}

// ---------------------------------------------------------------------------
// Kernel 2: chunked affine scan per (b,s). Sequences are contiguous in
// [b][s][n]; staged through padded shared for coalesced global access.
// ---------------------------------------------------------------------------
#define SP(i) ((i) + ((i) >> 4))

__global__ __launch_bounds__(256) void scan_kernel() {
    __shared__ float sd[4352], sv[4352];
    __shared__ float sA[256], sH[256];
    const int t = threadIdx.x;
    const size_t base = (size_t)blockIdx.x * SEQLEN;
    const int CH = SEQLEN / 256;   // 16

    // coalesced stage
#pragma unroll
    for (int i = 0; i < CH; i++) {
        int idx = i * 256 + t;
        sd[SP(idx)] = g_decay[base + idx];
        sv[SP(idx)] = g_bx[base + idx];
    }
    __syncthreads();

    float d[16], v[16];
#pragma unroll
    for (int i = 0; i < CH; i++) {
        int idx = t * CH + i;
        d[i] = sd[SP(idx)];
        v[i] = sv[SP(idx)];
    }

    float a = 1.f, h = 0.f;
#pragma unroll
    for (int i = 0; i < CH; i++) { h = fmaf(h, d[i], v[i]); a *= d[i]; }

    sA[t] = a; sH[t] = h;
    __syncthreads();
#pragma unroll
    for (int off = 1; off < 256; off <<= 1) {
        float pa = 1.f, ph = 0.f;
        const bool act = (t >= off);
        if (act) { pa = sA[t - off]; ph = sH[t - off]; }
        __syncthreads();
        if (act) {
            h = fmaf(a, ph, h);
            a = a * pa;
            sA[t] = a; sH[t] = h;
        }
        __syncthreads();
    }

    float hp = (t == 0) ? 0.f : sH[t - 1];
#pragma unroll
    for (int i = 0; i < CH; i++) {
        hp = fmaf(hp, d[i], v[i]);
        sv[SP(t * CH + i)] = hp;        // reuse sv as output staging
    }
    __syncthreads();
    // coalesced writeback
#pragma unroll
    for (int i = 0; i < CH; i++) {
        int idx = i * 256 + t;
        g_hs[base + idx] = sv[SP(idx)];
    }
}

// ---------------------------------------------------------------------------
// Kernel 3: y = hs @ C + x * D      (packed f32x2 over row pairs)
// Block: 64 rows x 512 cols, 256 threads; thread owns 2 cols x 2 rows.
// h[s][r..r+1] loads as a natural double from the [s][n] tile (no packing
// in the hot loop); C duplicated into packed regs once.
// ---------------------------------------------------------------------------
__global__ __launch_bounds__(256) void out_kernel(const float* __restrict__ x,
                                                  const float* __restrict__ C,
                                                  const float* __restrict__ D,
                                                  float* __restrict__ y) {
    __shared__ __align__(8) float sh[16][72];
    const int t = threadIdx.x;
    const int rb = blockIdx.x >> 1;
    const int half = blockIdx.x & 1;
    const int row0 = rb * 64;
    const int b = row0 >> 12, n0 = row0 & 4095;
    const int c0 = half * 512 + 2 * t;

    // stage hs tile [16 s][64 n] (coalesced)
#pragma unroll
    for (int i = 0; i < 4; i++) {
        int idx = i * 256 + t;
        int s = idx >> 6, j = idx & 63;
        sh[s][j] = g_hs[((size_t)(b * DSTATE + s)) * SEQLEN + n0 + j];
    }
    __syncthreads();

    // C duplicated into packed regs (loop-invariant)
    double cd0[16], cd1[16];
#pragma unroll
    for (int s = 0; s < 16; s++) {
        const float2 cv = *(const float2*)(C + (size_t)s * DMODEL + c0);
        cd0[s] = pk2(cv.x, cv.x);
        cd1[s] = pk2(cv.y, cv.y);
    }
    const float2 dv = *(const float2*)(D + c0);

#pragma unroll 4
    for (int r = 0; r < 64; r += 2) {
        const float2 xa = *(const float2*)(x + (size_t)(row0 + r) * DMODEL + c0);
        const float2 xb = *(const float2*)(x + (size_t)(row0 + r + 1) * DMODEL + c0);
        double acc0 = pk2(xa.x * dv.x, xb.x * dv.x);
        double acc1 = pk2(xa.y * dv.y, xb.y * dv.y);
#pragma unroll
        for (int s = 0; s < 16; s++) {
            const double h2 = *(const double*)&sh[s][r];   // (h[s][r], h[s][r+1])
            acc0 = fma2(h2, cd0[s], acc0);
            acc1 = fma2(h2, cd1[s], acc1);
        }
        float2 ya, yb;
        ya.x = lo2(acc0); ya.y = lo2(acc1);
        yb.x = hi2(acc0); yb.y = hi2(acc1);
        *(float2*)(y + (size_t)(row0 + r) * DMODEL + c0) = ya;
        *(float2*)(y + (size_t)(row0 + r + 1) * DMODEL + c0) = yb;
    }
}

extern "C" void kernel_launch(void* const* d_in, const int* in_sizes, int n_in,
                              void* d_out, int out_size) {
    const float* x    = (const float*)d_in[0];   // [4,4096,1024]
    const float* A    = (const float*)d_in[1];   // [1,16]
    const float* B_in = (const float*)d_in[2];   // [1024,16]
    const float* C    = (const float*)d_in[3];   // [16,1024]
    const float* D    = (const float*)d_in[4];   // [1024]
    float* y = (float*)d_out;                    // [4,4096,1024]

    bx_kernel<<<512, 256>>>(x, A, B_in);
    scan_kernel<<<64, 256>>>();
    out_kernel<<<512, 256>>>(x, C, D, y);
}

// round 3
// speedup vs baseline: 1.2982x; 1.0131x over previous
#include <cuda_runtime.h>

#define BATCH 4
#define SEQLEN 4096
#define DMODEL 1024
#define DSTATE 16
#define NROWS (BATCH*SEQLEN)

// Scratch in [b][s][n] layout (contiguous per scan sequence)
__device__ float g_bx[NROWS*DSTATE];
__device__ float g_decay[NROWS*DSTATE];
__device__ float g_hs[NROWS*DSTATE];

// ---- packed f32x2 helpers (FFMA2 only reachable via PTX) --------------------
__device__ __forceinline__ double pk2(float lo, float hi) {
    double d; asm("mov.b64 %0, {%1, %2};" : "=d"(d) : "f"(lo), "f"(hi)); return d;
}
__device__ __forceinline__ double fma2(double a, double b, double c) {
    double d; asm("fma.rn.f32x2 %0, %1, %2, %3;" : "=d"(d) : "d"(a), "d"(b), "d"(c)); return d;
}
__device__ __forceinline__ double add2(double a, double b) {
    double d; asm("add.rn.f32x2 %0, %1, %2;" : "=d"(d) : "d"(a), "d"(b)); return d;
}
__device__ __forceinline__ float lo2(double d) { return __int_as_float(__double2loint(d)); }
__device__ __forceinline__ float hi2(double d) { return __int_as_float(__double2hiint(d)); }

// ---------------------------------------------------------------------------
// Kernel 1: Bx = x @ B_in ; decay = exp(softplus(Bx) * -exp(A))
// Block: 256 threads, 32 rows (8 threads/row). Thread (rloc, c) covers
// e = c + 8k. x loads are coalesced LDG.32 (4 rows x 32B full sectors/warp).
// B chunk staged in shared, pitch 20 floats -> conflict-free double2 loads.
// Accumulation in 8 packed f32x2 regs; 3-stage shuffle reduce over c.
// Output written transposed to [b][s][n].
// ---------------------------------------------------------------------------
__global__ __launch_bounds__(256) void bx_kernel(const float* __restrict__ x,
                                                 const float* __restrict__ A,
                                                 const float* __restrict__ B_in) {
    __shared__ __align__(16) float sb[256 * 20];   // 20 KB (256-e chunk, pitch 20)
    __shared__ double sdump[32 * 8];               // 2 KB reduce spill

    const int t = threadIdx.x;
    const int c = t & 7;
    const int rloc = t >> 3;
    const int row = blockIdx.x * 32 + rloc;        // global row = b*4096 + n

    double acc[8];
#pragma unroll
    for (int i = 0; i < 8; i++) acc[i] = 0.0;      // bit-zero == (0.f,0.f)

    for (int ch = 0; ch < 4; ch++) {
        __syncthreads();
        // stage B[ch*256 .. +256) -> sb (pitch 20)
#pragma unroll
        for (int i = 0; i < 16; i++) {
            int idx = i * 256 + t;                 // 0..4095
            int e = idx >> 4, s = idx & 15;
            sb[e * 20 + s] = B_in[(size_t)(ch * 256 + e) * DSTATE + s];
        }
        __syncthreads();

        const float* xp = x + (size_t)row * DMODEL + ch * 256 + c;
#pragma unroll
        for (int k = 0; k < 32; k++) {
            const float xv = xp[k * 8];
            const double xx = pk2(xv, xv);
            const double2* bp = (const double2*)(sb + (c + k * 8) * 20);
            const double2 b0 = bp[0], b1 = bp[1], b2 = bp[2], b3 = bp[3];
            acc[0] = fma2(xx, b0.x, acc[0]);
            acc[1] = fma2(xx, b0.y, acc[1]);
            acc[2] = fma2(xx, b1.x, acc[2]);
            acc[3] = fma2(xx, b1.y, acc[3]);
            acc[4] = fma2(xx, b2.x, acc[4]);
            acc[5] = fma2(xx, b2.y, acc[5]);
            acc[6] = fma2(xx, b3.x, acc[6]);
            acc[7] = fma2(xx, b3.y, acc[7]);
        }
    }

    // reduce over the 8 c-lanes (xor within groups of 8)
#pragma unroll
    for (int off = 1; off < 8; off <<= 1) {
#pragma unroll
        for (int i = 0; i < 8; i++) {
            double o = __shfl_xor_sync(0xffffffffu, acc[i], off);
            acc[i] = add2(acc[i], o);
        }
    }

    __syncthreads();
    if (c == 0) {
#pragma unroll
        for (int i = 0; i < 8; i++) sdump[rloc * 8 + i] = acc[i];
    }
    __syncthreads();

    // thread handles s = 2c, 2c+1 for its row
    const double mysum = sdump[rloc * 8 + c];
    const float bx0 = lo2(mysum), bx1 = hi2(mysum);
    const int s0 = 2 * c;
    const float an0 = -expf(A[s0]);
    const float an1 = -expf(A[s0 + 1]);
    const float sp0 = (bx0 > 20.f) ? bx0 : log1pf(expf(bx0));
    const float sp1 = (bx1 > 20.f) ? bx1 : log1pf(expf(bx1));
    const float d0 = expf(sp0 * an0);
    const float d1 = expf(sp1 * an1);

    const int b = row >> 12, n = row & 4095;
    const size_t o0 = ((size_t)(b * DSTATE + s0)) * SEQLEN + n;
    g_bx[o0] = bx0;            g_bx[o0 + SEQLEN] = bx1;
    g_decay[o0] = d0;          g_decay[o0 + SEQLEN] = d1;
}

// ---------------------------------------------------------------------------
// Kernel 2: chunked affine scan per (b,s). Sequences are contiguous in
// [b][s][n]; staged through padded shared for coalesced global access.
// ---------------------------------------------------------------------------
#define SP(i) ((i) + ((i) >> 4))

__global__ __launch_bounds__(256) void scan_kernel() {
    __shared__ float sd[4352], sv[4352];
    __shared__ float sA[256], sH[256];
    const int t = threadIdx.x;
    const size_t base = (size_t)blockIdx.x * SEQLEN;
    const int CH = SEQLEN / 256;   // 16

    // coalesced stage
#pragma unroll
    for (int i = 0; i < CH; i++) {
        int idx = i * 256 + t;
        sd[SP(idx)] = g_decay[base + idx];
        sv[SP(idx)] = g_bx[base + idx];
    }
    __syncthreads();

    float d[16], v[16];
#pragma unroll
    for (int i = 0; i < CH; i++) {
        int idx = t * CH + i;
        d[i] = sd[SP(idx)];
        v[i] = sv[SP(idx)];
    }

    float a = 1.f, h = 0.f;
#pragma unroll
    for (int i = 0; i < CH; i++) { h = fmaf(h, d[i], v[i]); a *= d[i]; }

    sA[t] = a; sH[t] = h;
    __syncthreads();
#pragma unroll
    for (int off = 1; off < 256; off <<= 1) {
        float pa = 1.f, ph = 0.f;
        const bool act = (t >= off);
        if (act) { pa = sA[t - off]; ph = sH[t - off]; }
        __syncthreads();
        if (act) {
            h = fmaf(a, ph, h);
            a = a * pa;
            sA[t] = a; sH[t] = h;
        }
        __syncthreads();
    }

    float hp = (t == 0) ? 0.f : sH[t - 1];
#pragma unroll
    for (int i = 0; i < CH; i++) {
        hp = fmaf(hp, d[i], v[i]);
        sv[SP(t * CH + i)] = hp;        // reuse sv as output staging
    }
    __syncthreads();
    // coalesced writeback
#pragma unroll
    for (int i = 0; i < CH; i++) {
        int idx = i * 256 + t;
        g_hs[base + idx] = sv[SP(idx)];
    }
}

// ---------------------------------------------------------------------------
// Kernel 3: y = hs @ C + x * D      (packed f32x2 over row pairs)
// Block: 64 rows x 512 cols, 256 threads; thread owns 2 cols x 2 rows.
// h[s][r..r+1] loads as a natural double from the [s][n] tile (no packing
// in the hot loop); C duplicated into packed regs once.
// ---------------------------------------------------------------------------
__global__ __launch_bounds__(256) void out_kernel(const float* __restrict__ x,
                                                  const float* __restrict__ C,
                                                  const float* __restrict__ D,
                                                  float* __restrict__ y) {
    __shared__ __align__(8) float sh[16][72];
    const int t = threadIdx.x;
    const int rb = blockIdx.x >> 1;
    const int half = blockIdx.x & 1;
    const int row0 = rb * 64;
    const int b = row0 >> 12, n0 = row0 & 4095;
    const int c0 = half * 512 + 2 * t;

    // stage hs tile [16 s][64 n] (coalesced)
#pragma unroll
    for (int i = 0; i < 4; i++) {
        int idx = i * 256 + t;
        int s = idx >> 6, j = idx & 63;
        sh[s][j] = g_hs[((size_t)(b * DSTATE + s)) * SEQLEN + n0 + j];
    }
    __syncthreads();

    // C duplicated into packed regs (loop-invariant)
    double cd0[16], cd1[16];
#pragma unroll
    for (int s = 0; s < 16; s++) {
        const float2 cv = *(const float2*)(C + (size_t)s * DMODEL + c0);
        cd0[s] = pk2(cv.x, cv.x);
        cd1[s] = pk2(cv.y, cv.y);
    }
    const float2 dv = *(const float2*)(D + c0);

#pragma unroll 4
    for (int r = 0; r < 64; r += 2) {
        const float2 xa = *(const float2*)(x + (size_t)(row0 + r) * DMODEL + c0);
        const float2 xb = *(const float2*)(x + (size_t)(row0 + r + 1) * DMODEL + c0);
        double acc0 = pk2(xa.x * dv.x, xb.x * dv.x);
        double acc1 = pk2(xa.y * dv.y, xb.y * dv.y);
#pragma unroll
        for (int s = 0; s < 16; s++) {
            const double h2 = *(const double*)&sh[s][r];   // (h[s][r], h[s][r+1])
            acc0 = fma2(h2, cd0[s], acc0);
            acc1 = fma2(h2, cd1[s], acc1);
        }
        float2 ya, yb;
        ya.x = lo2(acc0); ya.y = lo2(acc1);
        yb.x = hi2(acc0); yb.y = hi2(acc1);
        *(float2*)(y + (size_t)(row0 + r) * DMODEL + c0) = ya;
        *(float2*)(y + (size_t)(row0 + r + 1) * DMODEL + c0) = yb;
    }
}

extern "C" void kernel_launch(void* const* d_in, const int* in_sizes, int n_in,
                              void* d_out, int out_size) {
    const float* x    = (const float*)d_in[0];   // [4,4096,1024]
    const float* A    = (const float*)d_in[1];   // [1,16]
    const float* B_in = (const float*)d_in[2];   // [1024,16]
    const float* C    = (const float*)d_in[3];   // [16,1024]
    const float* D    = (const float*)d_in[4];   // [1024]
    float* y = (float*)d_out;                    // [4,4096,1024]

    bx_kernel<<<512, 256>>>(x, A, B_in);
    scan_kernel<<<64, 256>>>();
    out_kernel<<<512, 256>>>(x, C, D, y);
}

// round 4
// speedup vs baseline: 1.7691x; 1.3627x over previous
#include <cuda_runtime.h>

#define BATCH 4
#define SEQLEN 4096
#define DMODEL 1024
#define DSTATE 16
#define NROWS (BATCH*SEQLEN)
#define NCHUNK 64                 // chunks per sequence; chunk = 64 timesteps

// Scratch in [b][s][n] layout (contiguous per sequence)
__device__ float g_bx[NROWS*DSTATE];
__device__ float g_decay[NROWS*DSTATE];
__device__ float g_cA[BATCH*DSTATE*NCHUNK];   // per-chunk decay product
__device__ float g_cH[BATCH*DSTATE*NCHUNK];   // per-chunk h (seed 0)
__device__ float g_hpre[BATCH*DSTATE*NCHUNK]; // exclusive prefix state per chunk

// ---- packed f32x2 helpers ---------------------------------------------------
__device__ __forceinline__ double pk2(float lo, float hi) {
    double d; asm("mov.b64 %0, {%1, %2};" : "=d"(d) : "f"(lo), "f"(hi)); return d;
}
__device__ __forceinline__ double fma2(double a, double b, double c) {
    double d; asm("fma.rn.f32x2 %0, %1, %2, %3;" : "=d"(d) : "d"(a), "d"(b), "d"(c)); return d;
}
__device__ __forceinline__ double add2(double a, double b) {
    double d; asm("add.rn.f32x2 %0, %1, %2;" : "=d"(d) : "d"(a), "d"(b)); return d;
}
__device__ __forceinline__ float lo2(double d) { return __int_as_float(__double2loint(d)); }
__device__ __forceinline__ float hi2(double d) { return __int_as_float(__double2hiint(d)); }

// ---------------------------------------------------------------------------
// Kernel 1: Bx = x @ B_in ; decay = exp(softplus(Bx) * -exp(A))
// 256 threads / 64 rows per block: thread (c = t&15, rgrp = t>>4) handles
// 4 rows, e-stripe e = c + 16k. B staged in shared at pitch 18 floats
// (18c mod 32 is a permutation of 16 lanes -> conflict-free LDS.64).
// Each B smem read amortized over 4 rows (4x less LDS traffic than before).
// Also emits per-chunk (64-step) affine scan summaries.
// ---------------------------------------------------------------------------
__global__ __launch_bounds__(256) void bx_kernel(const float* __restrict__ x,
                                                 const float* __restrict__ A,
                                                 const float* __restrict__ B_in) {
    __shared__ __align__(16) float sb[256 * 18];   // 18 KB B chunk
    __shared__ double sdump[64][8];                // 4 KB reduced sums
    __shared__ float sdec[DSTATE][65];             // decay [s][row]
    __shared__ float sbxs[DSTATE][65];             // bx    [s][row]

    const int t = threadIdx.x;
    const int c = t & 15;
    const int rgrp = t >> 4;
    const int row0 = blockIdx.x * 64 + rgrp * 4;

    double acc[4][8];
#pragma unroll
    for (int r = 0; r < 4; r++)
#pragma unroll
        for (int j = 0; j < 8; j++) acc[r][j] = 0.0;

    for (int ch = 0; ch < 4; ch++) {
        __syncthreads();
#pragma unroll
        for (int i = 0; i < 16; i++) {
            int idx = i * 256 + t;                 // 0..4095
            int e = idx >> 4, s = idx & 15;
            sb[e * 18 + s] = B_in[(size_t)(ch * 256 + e) * DSTATE + s];
        }
        __syncthreads();

        const float* xp = x + (size_t)row0 * DMODEL + ch * 256 + c;
#pragma unroll
        for (int k = 0; k < 16; k++) {
            double xx[4];
#pragma unroll
            for (int r = 0; r < 4; r++) {
                const float xv = xp[r * DMODEL + k * 16];
                xx[r] = pk2(xv, xv);
            }
            const double* bp = (const double*)(sb + (c + k * 16) * 18);
            double bv[8];
#pragma unroll
            for (int j = 0; j < 8; j++) bv[j] = bp[j];
#pragma unroll
            for (int r = 0; r < 4; r++)
#pragma unroll
                for (int j = 0; j < 8; j++)
                    acc[r][j] = fma2(xx[r], bv[j], acc[r][j]);
        }
    }

    // reduce across the 16 c-lanes
#pragma unroll
    for (int off = 1; off < 16; off <<= 1) {
#pragma unroll
        for (int r = 0; r < 4; r++)
#pragma unroll
            for (int j = 0; j < 8; j++) {
                double o = __shfl_xor_sync(0xffffffffu, acc[r][j], off);
                acc[r][j] = add2(acc[r][j], o);
            }
    }

    __syncthreads();
    if (c == 0) {
#pragma unroll
        for (int r = 0; r < 4; r++)
#pragma unroll
            for (int j = 0; j < 8; j++) sdump[rgrp * 4 + r][j] = acc[r][j];
    }
    __syncthreads();

    // thread t: row rl = t>>2, s-quad q = t&3
    {
        const int rl = t >> 2, q = t & 3;
        const double v0 = sdump[rl][2 * q];
        const double v1 = sdump[rl][2 * q + 1];
        float bxv[4] = { lo2(v0), hi2(v0), lo2(v1), hi2(v1) };
#pragma unroll
        for (int j = 0; j < 4; j++) {
            const int s = 4 * q + j;
            const float an = -expf(A[s]);
            const float bx = bxv[j];
            const float sp = (bx > 20.f) ? bx : log1pf(expf(bx));
            sdec[s][rl] = expf(sp * an);
            sbxs[s][rl] = bx;
        }
    }
    __syncthreads();

    const int b = blockIdx.x >> 6;
    const int n0 = (blockIdx.x * 64) & (SEQLEN - 1);
    // coalesced global writes of bx / decay in [b][s][n]
#pragma unroll
    for (int i = 0; i < 4; i++) {
        int idx = i * 256 + t;
        int s = idx >> 6, j = idx & 63;
        size_t o = ((size_t)(b * DSTATE + s)) * SEQLEN + n0 + j;
        g_bx[o] = sbxs[s][j];
        g_decay[o] = sdec[s][j];
    }
    // per-chunk summary (this block IS one chunk per (b,s))
    if (t < DSTATE) {
        float a = 1.f, h = 0.f;
#pragma unroll
        for (int j = 0; j < 64; j++) {
            const float d = sdec[t][j];
            h = fmaf(h, d, sbxs[t][j]);
            a *= d;
        }
        const int so = (b * DSTATE + t) * NCHUNK + (n0 >> 6);
        g_cA[so] = a;
        g_cH[so] = h;
    }
}

// ---------------------------------------------------------------------------
// Kernel 2: scan 64 chunk summaries per (b,s); write EXCLUSIVE prefix state.
// ---------------------------------------------------------------------------
__global__ __launch_bounds__(64) void chunkscan_kernel() {
    __shared__ float sA[64], sH[64];
    const int t = threadIdx.x;
    const int seq = blockIdx.x;                    // b*16 + s
    float a = g_cA[seq * NCHUNK + t];
    float h = g_cH[seq * NCHUNK + t];
    sA[t] = a; sH[t] = h;
    __syncthreads();
#pragma unroll
    for (int off = 1; off < 64; off <<= 1) {
        float pa = 1.f, ph = 0.f;
        const bool act = (t >= off);
        if (act) { pa = sA[t - off]; ph = sH[t - off]; }
        __syncthreads();
        if (act) {
            h = fmaf(a, ph, h);
            a = a * pa;
            sA[t] = a; sH[t] = h;
        }
        __syncthreads();
    }
    g_hpre[seq * NCHUNK + t] = (t == 0) ? 0.f : sH[t - 1];
}

// ---------------------------------------------------------------------------
// Kernel 3: replay scan for this 64-row chunk (from prefix) + y = hs@C + x*D
// Block: 64 rows x 512 cols; thread owns 2 cols x 2 rows (packed f32x2).
// ---------------------------------------------------------------------------
__global__ __launch_bounds__(256) void out_kernel(const float* __restrict__ x,
                                                  const float* __restrict__ C,
                                                  const float* __restrict__ D,
                                                  float* __restrict__ y) {
    __shared__ float sd[DSTATE][65], sv[DSTATE][65];
    __shared__ __align__(8) float shh[DSTATE][72];
    const int t = threadIdx.x;
    const int rb = blockIdx.x >> 1;
    const int half = blockIdx.x & 1;
    const int row0 = rb * 64;
    const int b = row0 >> 12, n0 = row0 & (SEQLEN - 1);
    const int chunk = n0 >> 6;
    const int c0 = half * 512 + 2 * t;

    // stage decay/bx tiles [16 s][64 n] (coalesced)
#pragma unroll
    for (int i = 0; i < 4; i++) {
        int idx = i * 256 + t;
        int s = idx >> 6, j = idx & 63;
        size_t o = ((size_t)(b * DSTATE + s)) * SEQLEN + n0 + j;
        sd[s][j] = g_decay[o];
        sv[s][j] = g_bx[o];
    }
    __syncthreads();

    // replay the recurrence for this chunk from the exclusive prefix
    if (t < DSTATE) {
        float h = g_hpre[(b * DSTATE + t) * NCHUNK + chunk];
#pragma unroll
        for (int j = 0; j < 64; j++) {
            h = fmaf(h, sd[t][j], sv[t][j]);
            shh[t][j] = h;
        }
    }
    __syncthreads();

    // C duplicated into packed regs (loop-invariant)
    double cd0[16], cd1[16];
#pragma unroll
    for (int s = 0; s < 16; s++) {
        const float2 cv = *(const float2*)(C + (size_t)s * DMODEL + c0);
        cd0[s] = pk2(cv.x, cv.x);
        cd1[s] = pk2(cv.y, cv.y);
    }
    const float2 dv = *(const float2*)(D + c0);

#pragma unroll 4
    for (int r = 0; r < 64; r += 2) {
        const float2 xa = *(const float2*)(x + (size_t)(row0 + r) * DMODEL + c0);
        const float2 xb = *(const float2*)(x + (size_t)(row0 + r + 1) * DMODEL + c0);
        double acc0 = pk2(xa.x * dv.x, xb.x * dv.x);
        double acc1 = pk2(xa.y * dv.y, xb.y * dv.y);
#pragma unroll
        for (int s = 0; s < 16; s++) {
            const double h2 = *(const double*)&shh[s][r];   // (h[s][r], h[s][r+1])
            acc0 = fma2(h2, cd0[s], acc0);
            acc1 = fma2(h2, cd1[s], acc1);
        }
        float2 ya, yb;
        ya.x = lo2(acc0); ya.y = lo2(acc1);
        yb.x = hi2(acc0); yb.y = hi2(acc1);
        *(float2*)(y + (size_t)(row0 + r) * DMODEL + c0) = ya;
        *(float2*)(y + (size_t)(row0 + r + 1) * DMODEL + c0) = yb;
    }
}

extern "C" void kernel_launch(void* const* d_in, const int* in_sizes, int n_in,
                              void* d_out, int out_size) {
    const float* x    = (const float*)d_in[0];   // [4,4096,1024]
    const float* A    = (const float*)d_in[1];   // [1,16]
    const float* B_in = (const float*)d_in[2];   // [1024,16]
    const float* C    = (const float*)d_in[3];   // [16,1024]
    const float* D    = (const float*)d_in[4];   // [1024]
    float* y = (float*)d_out;                    // [4,4096,1024]

    bx_kernel<<<256, 256>>>(x, A, B_in);
    chunkscan_kernel<<<64, 64>>>();
    out_kernel<<<512, 256>>>(x, C, D, y);
}